// round 4
// baseline (speedup 1.0000x reference)
#include <cuda_runtime.h>
#include <math.h>

#define N_B   4
#define N_T   1024
#define N_D   768
#define N_H   12
#define N_L   6
#define N_DF  3072
#define N_V   32000
#define N_BT  (N_B*N_T)

typedef unsigned long long u64;

// ---- packed f32x2 helpers (FFMA2: 2x fp32 throughput, PTX-only per SASS_QUICKREF) ----
__device__ __forceinline__ u64 pk2(float lo, float hi){
    u64 r; asm("mov.b64 %0, {%1, %2};" : "=l"(r) : "f"(lo), "f"(hi)); return r;
}
__device__ __forceinline__ void upk2(u64 v, float& lo, float& hi){
    asm("mov.b64 {%0, %1}, %2;" : "=f"(lo), "=f"(hi) : "l"(v));
}
__device__ __forceinline__ void ffma2(u64& d, u64 a, u64 b){
    asm("fma.rn.f32x2 %0, %1, %2, %0;" : "+l"(d) : "l"(a), "l"(b));
}

// ---- scratch (device globals; no allocation allowed) ----
__device__ float g_x  [N_BT*N_D];
__device__ float g_h  [N_BT*N_D];
__device__ float g_q  [N_BT*N_D];
__device__ float g_k  [N_BT*N_D];
__device__ float g_v  [N_BT*N_D];
__device__ float g_att[N_BT*N_D];
__device__ float g_ff [N_BT*N_DF];

// =================== embedding ===================
__global__ __launch_bounds__(256) void embed_kernel(const int* __restrict__ idx,
                                                    const float* __restrict__ tok,
                                                    const float* __restrict__ pos){
    int bt = blockIdx.x;
    int t  = bt & (N_T-1);
    int token = idx[bt];
    const float* tp = tok + (size_t)token*N_D;
    const float* pp = pos + (size_t)t*N_D;
    float* xp = g_x + (size_t)bt*N_D;
    for(int d = threadIdx.x; d < N_D; d += 256)
        xp[d] = tp[d] + pp[d];
}

// =================== layernorm (one block per row, D=768) ===================
__global__ __launch_bounds__(256) void ln_kernel(const float* __restrict__ in,
                                                 float* __restrict__ out,
                                                 const float* __restrict__ gam,
                                                 const float* __restrict__ bet){
    int row = blockIdx.x;
    int tid = threadIdx.x;
    const float* xr = in + (size_t)row*N_D;
    float v0 = xr[tid], v1 = xr[tid+256], v2 = xr[tid+512];
    __shared__ float red[8];
    float s = v0+v1+v2;
    #pragma unroll
    for(int o=16;o>0;o>>=1) s += __shfl_xor_sync(0xffffffffu, s, o);
    if((tid&31)==0) red[tid>>5] = s;
    __syncthreads();
    float tot = 0.f;
    #pragma unroll
    for(int w=0;w<8;w++) tot += red[w];
    float mu = tot * (1.f/N_D);
    float d0=v0-mu, d1=v1-mu, d2=v2-mu;
    float s2 = d0*d0 + d1*d1 + d2*d2;
    #pragma unroll
    for(int o=16;o>0;o>>=1) s2 += __shfl_xor_sync(0xffffffffu, s2, o);
    __syncthreads();
    if((tid&31)==0) red[tid>>5] = s2;
    __syncthreads();
    float tot2 = 0.f;
    #pragma unroll
    for(int w=0;w<8;w++) tot2 += red[w];
    float rstd = rsqrtf(tot2*(1.f/N_D) + 1e-5f);
    float* orow = out + (size_t)row*N_D;
    orow[tid]     = d0*rstd*gam[tid]     + bet[tid];
    orow[tid+256] = d1*rstd*gam[tid+256] + bet[tid+256];
    orow[tid+512] = d2*rstd*gam[tid+512] + bet[tid+512];
}

// =================== GEMM: C[M,N] = A[M,K] @ B[K,N] (+epilogue) ===================
// 128x128x16 tile, 256 threads, 8x8 per thread, f32x2-packed FMAs.
// EPI: 0 = none, 1 = +bias, 2 = +bias +residual, 3 = +bias then exact GELU
template<int EPI>
__global__ __launch_bounds__(256) void gemm_kernel(
        const float* __restrict__ A, const float* __restrict__ B,
        const float* __restrict__ bias, const float* res,
        float* C, int M, int N, int K){
    __shared__ float As[16][132];   // A tile transposed, padded (2-way max conflicts)
    __shared__ float Bs[16][128];
    const int tid = threadIdx.x;
    const int tr = tid >> 4, tc = tid & 15;
    const int mBase = blockIdx.x * 128;
    const int nBase = blockIdx.y * 128;
    const float* Ap = A + (size_t)mBase * K;
    const float* Bp = B + nBase;

    u64 acc2[8][4];
    #pragma unroll
    for(int i=0;i<8;i++)
        #pragma unroll
        for(int j=0;j<4;j++) acc2[i][j] = 0ull;

    for(int k0 = 0; k0 < K; k0 += 16){
        #pragma unroll
        for(int v=tid; v<512; v+=256){        // A tile: 128x16 as 512 float4
            int row = v >> 2, c = (v & 3) << 2;
            float4 f = *(const float4*)(Ap + (size_t)row*K + k0 + c);
            As[c+0][row]=f.x; As[c+1][row]=f.y; As[c+2][row]=f.z; As[c+3][row]=f.w;
        }
        #pragma unroll
        for(int v=tid; v<512; v+=256){        // B tile: 16x128 as 512 float4
            int row = v >> 5, c = (v & 31) << 2;
            *(float4*)&Bs[row][c] = *(const float4*)(Bp + (size_t)(k0+row)*N + c);
        }
        __syncthreads();
        #pragma unroll
        for(int kk=0;kk<16;kk++){
            float4 aA = *(const float4*)&As[kk][tr*8];
            float4 aB = *(const float4*)&As[kk][tr*8+4];
            float4 bA = *(const float4*)&Bs[kk][tc*8];
            float4 bB = *(const float4*)&Bs[kk][tc*8+4];
            u64 a2[8] = { pk2(aA.x,aA.x), pk2(aA.y,aA.y), pk2(aA.z,aA.z), pk2(aA.w,aA.w),
                          pk2(aB.x,aB.x), pk2(aB.y,aB.y), pk2(aB.z,aB.z), pk2(aB.w,aB.w) };
            u64 b2[4] = { pk2(bA.x,bA.y), pk2(bA.z,bA.w), pk2(bB.x,bB.y), pk2(bB.z,bB.w) };
            #pragma unroll
            for(int i=0;i<8;i++)
                #pragma unroll
                for(int j=0;j<4;j++) ffma2(acc2[i][j], a2[i], b2[j]);
        }
        __syncthreads();
    }

    float bvals[8];
    if(EPI != 0){
        #pragma unroll
        for(int j=0;j<8;j++) bvals[j] = bias[nBase + tc*8 + j];
    }
    #pragma unroll
    for(int i=0;i<8;i++){
        int m = mBase + tr*8 + i;
        size_t off = (size_t)m*N + nBase + tc*8;
        float c[8];
        #pragma unroll
        for(int j=0;j<4;j++) upk2(acc2[i][j], c[2*j], c[2*j+1]);
        if(EPI != 0){
            #pragma unroll
            for(int j=0;j<8;j++) c[j] += bvals[j];
        }
        if(EPI == 2){
            float4 r0 = *(const float4*)(res + off);
            float4 r1 = *(const float4*)(res + off + 4);
            c[0]+=r0.x; c[1]+=r0.y; c[2]+=r0.z; c[3]+=r0.w;
            c[4]+=r1.x; c[5]+=r1.y; c[6]+=r1.z; c[7]+=r1.w;
        }
        if(EPI == 3){
            #pragma unroll
            for(int j=0;j<8;j++) c[j] = 0.5f*c[j]*(1.f + erff(c[j]*0.70710678118654752f));
        }
        *(float4*)(C + off)     = make_float4(c[0],c[1],c[2],c[3]);
        *(float4*)(C + off + 4) = make_float4(c[4],c[5],c[6],c[7]);
    }
}

// =================== fused causal flash attention ===================
// grid: (T/64 q-tiles, B*H). 256 threads as 16x16, each 4x4 micro-tile.
// Q/K/V/P 64x64 tiles in SMEM (pad 65), online softmax, single pass over keys.
#define APAD 65
#define ATT_SMEM (3*64*APAD*4)

__global__ __launch_bounds__(256) void attn_kernel(const float* __restrict__ Q,
                                                   const float* __restrict__ K,
                                                   const float* __restrict__ V,
                                                   float* __restrict__ O){
    extern __shared__ float sm[];
    float* Qs  = sm;
    float* KVs = sm + 64*APAD;
    float* Ps  = sm + 2*64*APAD;
    const int qtile = blockIdx.x;
    const int bh = blockIdx.y;
    const int b = bh / N_H, h = bh % N_H;
    const int tid = threadIdx.x;
    const int tr = tid >> 4, tc = tid & 15;
    const size_t headoff = (size_t)b*N_T*N_D + (size_t)h*64;
    const float* Qb = Q + headoff;
    const float* Kb = K + headoff;
    const float* Vb = V + headoff;

    for(int v4 = tid; v4 < 1024; v4 += 256){
        int r = v4 >> 4, c = (v4 & 15) << 2;
        float4 f = *(const float4*)(Qb + (size_t)(qtile*64 + r)*N_D + c);
        float* d = Qs + r*APAD + c;
        d[0]=f.x; d[1]=f.y; d[2]=f.z; d[3]=f.w;
    }

    float m_[4], l_[4], acc[4][4];
    #pragma unroll
    for(int i=0;i<4;i++){
        m_[i] = -1e30f; l_[i] = 0.f;
        #pragma unroll
        for(int j=0;j<4;j++) acc[i][j] = 0.f;
    }

    for(int kt = 0; kt <= qtile; kt++){
        // ---- load K tile ----
        for(int v4 = tid; v4 < 1024; v4 += 256){
            int r = v4 >> 4, c = (v4 & 15) << 2;
            float4 f = *(const float4*)(Kb + (size_t)(kt*64 + r)*N_D + c);
            float* d = KVs + r*APAD + c;
            d[0]=f.x; d[1]=f.y; d[2]=f.z; d[3]=f.w;
        }
        __syncthreads();

        // ---- S = Q K^T ----
        float s[4][4];
        #pragma unroll
        for(int i=0;i<4;i++)
            #pragma unroll
            for(int j=0;j<4;j++) s[i][j] = 0.f;
        #pragma unroll 8
        for(int kk=0;kk<64;kk++){
            float qa[4], ka[4];
            #pragma unroll
            for(int i=0;i<4;i++) qa[i] = Qs[(tr*4+i)*APAD + kk];
            #pragma unroll
            for(int j=0;j<4;j++) ka[j] = KVs[(tc*4+j)*APAD + kk];
            #pragma unroll
            for(int i=0;i<4;i++)
                #pragma unroll
                for(int j=0;j<4;j++) s[i][j] += qa[i]*ka[j];
        }
        const float scl = 0.125f;  // 1/sqrt(64)
        if(kt == qtile){
            #pragma unroll
            for(int i=0;i<4;i++)
                #pragma unroll
                for(int j=0;j<4;j++)
                    s[i][j] = (tc*4+j <= tr*4+i) ? s[i][j]*scl : -1e30f;
        } else {
            #pragma unroll
            for(int i=0;i<4;i++)
                #pragma unroll
                for(int j=0;j<4;j++) s[i][j] *= scl;
        }

        // ---- online softmax (row reduce across 16 tc lanes via shfl) ----
        #pragma unroll
        for(int i=0;i<4;i++){
            float rm = fmaxf(fmaxf(s[i][0],s[i][1]), fmaxf(s[i][2],s[i][3]));
            #pragma unroll
            for(int o=8;o>0;o>>=1) rm = fmaxf(rm, __shfl_xor_sync(0xffffffffu, rm, o));
            float mn = fmaxf(m_[i], rm);
            float corr = expf(m_[i] - mn);
            m_[i] = mn;
            float rs = 0.f;
            #pragma unroll
            for(int j=0;j<4;j++){ float p = expf(s[i][j] - mn); s[i][j] = p; rs += p; }
            #pragma unroll
            for(int o=8;o>0;o>>=1) rs += __shfl_xor_sync(0xffffffffu, rs, o);
            l_[i] = l_[i]*corr + rs;
            #pragma unroll
            for(int j=0;j<4;j++){ acc[i][j] *= corr; Ps[(tr*4+i)*APAD + tc*4+j] = s[i][j]; }
        }
        __syncthreads();   // Ps written, K-tile reads done

        // ---- load V tile (reuse KVs) ----
        for(int v4 = tid; v4 < 1024; v4 += 256){
            int r = v4 >> 4, c = (v4 & 15) << 2;
            float4 f = *(const float4*)(Vb + (size_t)(kt*64 + r)*N_D + c);
            float* d = KVs + r*APAD + c;
            d[0]=f.x; d[1]=f.y; d[2]=f.z; d[3]=f.w;
        }
        __syncthreads();

        // ---- O += P V ----
        #pragma unroll 8
        for(int kk=0;kk<64;kk++){
            float pa[4], va[4];
            #pragma unroll
            for(int i=0;i<4;i++) pa[i] = Ps[(tr*4+i)*APAD + kk];
            #pragma unroll
            for(int j=0;j<4;j++) va[j] = KVs[kk*APAD + tc*4 + j];
            #pragma unroll
            for(int i=0;i<4;i++)
                #pragma unroll
                for(int j=0;j<4;j++) acc[i][j] += pa[i]*va[j];
        }
        __syncthreads();
    }

    float* Ob = O + headoff;
    #pragma unroll
    for(int i=0;i<4;i++){
        float inv = 1.f / l_[i];
        int r = qtile*64 + tr*4 + i;
        *(float4*)(Ob + (size_t)r*N_D + tc*4) =
            make_float4(acc[i][0]*inv, acc[i][1]*inv, acc[i][2]*inv, acc[i][3]*inv);
    }
}

// =================== host orchestration ===================
extern "C" void kernel_launch(void* const* d_in, const int* in_sizes, int n_in,
                              void* d_out, int out_size){
    const int*   idx   = (const int*)  d_in[0];
    const float* tok   = (const float*)d_in[1];
    const float* pos   = (const float*)d_in[2];
    const float* Wq    = (const float*)d_in[3];
    const float* Wk    = (const float*)d_in[4];
    const float* Wv    = (const float*)d_in[5];
    const float* Wo    = (const float*)d_in[6];
    const float* bo    = (const float*)d_in[7];
    const float* W1    = (const float*)d_in[8];
    const float* b1    = (const float*)d_in[9];
    const float* W2    = (const float*)d_in[10];
    const float* b2    = (const float*)d_in[11];
    const float* ln1g  = (const float*)d_in[12];
    const float* ln1b  = (const float*)d_in[13];
    const float* ln2g  = (const float*)d_in[14];
    const float* ln2b  = (const float*)d_in[15];
    const float* lnfg  = (const float*)d_in[16];
    const float* lnfb  = (const float*)d_in[17];
    const float* headW = (const float*)d_in[18];
    const float* headb = (const float*)d_in[19];
    float* out = (float*)d_out;

    float *x,*h,*q,*k,*v,*att,*ff;
    cudaGetSymbolAddress((void**)&x,   g_x);
    cudaGetSymbolAddress((void**)&h,   g_h);
    cudaGetSymbolAddress((void**)&q,   g_q);
    cudaGetSymbolAddress((void**)&k,   g_k);
    cudaGetSymbolAddress((void**)&v,   g_v);
    cudaGetSymbolAddress((void**)&att, g_att);
    cudaGetSymbolAddress((void**)&ff,  g_ff);

    cudaFuncSetAttribute(attn_kernel, cudaFuncAttributeMaxDynamicSharedMemorySize, ATT_SMEM);

    embed_kernel<<<N_BT, 256>>>(idx, tok, pos);

    const dim3 gDD(N_BT/128, N_D/128);    // 32 x 6
    const dim3 gDF(N_BT/128, N_DF/128);   // 32 x 24
    const dim3 gAtt(N_T/64, N_B*N_H);     // 16 x 48
    for(int l=0;l<N_L;l++){
        ln_kernel<<<N_BT,256>>>(x, h, ln1g + l*N_D, ln1b + l*N_D);
        gemm_kernel<0><<<gDD,256>>>(h, Wq + (size_t)l*N_D*N_D, nullptr, nullptr, q, N_BT, N_D, N_D);
        gemm_kernel<0><<<gDD,256>>>(h, Wk + (size_t)l*N_D*N_D, nullptr, nullptr, k, N_BT, N_D, N_D);
        gemm_kernel<0><<<gDD,256>>>(h, Wv + (size_t)l*N_D*N_D, nullptr, nullptr, v, N_BT, N_D, N_D);
        attn_kernel<<<gAtt,256,ATT_SMEM>>>(q, k, v, att);
        gemm_kernel<2><<<gDD,256>>>(att, Wo + (size_t)l*N_D*N_D, bo + l*N_D, x, x, N_BT, N_D, N_D);
        ln_kernel<<<N_BT,256>>>(x, h, ln2g + l*N_D, ln2b + l*N_D);
        gemm_kernel<3><<<gDF,256>>>(h, W1 + (size_t)l*N_D*N_DF, b1 + l*N_DF, nullptr, ff, N_BT, N_DF, N_D);
        gemm_kernel<2><<<gDD,256>>>(ff, W2 + (size_t)l*N_DF*N_D, b2 + l*N_D, x, x, N_BT, N_D, N_DF);
    }
    ln_kernel<<<N_BT,256>>>(x, h, lnfg, lnfb);
    gemm_kernel<1><<<dim3(N_BT/128, N_V/128),256>>>(h, headW, headb, nullptr, out, N_BT, N_V, N_D);
}

// round 6
// speedup vs baseline: 2.1415x; 2.1415x over previous
#include <cuda_runtime.h>
#include <cuda_bf16.h>
#include <math.h>
#include <stdint.h>

#define N_Bc  4
#define N_T   1024
#define N_D   768
#define N_H   12
#define N_L   6
#define N_DF  3072
#define N_V   32000
#define N_BT  (N_Bc*N_T)
#define N_QKV (3*N_D)

// ============================ PTX helpers ============================
__device__ __forceinline__ uint32_t smem_u32(const void* p){
    uint32_t a;
    asm("{ .reg .u64 t; cvta.to.shared.u64 t, %1; cvt.u32.u64 %0, t; }" : "=r"(a) : "l"(p));
    return a;
}
__device__ __forceinline__ void ldsm_x4(uint32_t* r, uint32_t addr){
    asm volatile("ldmatrix.sync.aligned.m8n8.x4.shared.b16 {%0,%1,%2,%3}, [%4];"
      : "=r"(r[0]),"=r"(r[1]),"=r"(r[2]),"=r"(r[3]) : "r"(addr));
}
__device__ __forceinline__ void ldsm_x2(uint32_t* r, uint32_t addr){
    asm volatile("ldmatrix.sync.aligned.m8n8.x2.shared.b16 {%0,%1}, [%2];"
      : "=r"(r[0]),"=r"(r[1]) : "r"(addr));
}
__device__ __forceinline__ void mma_bf16(float* c, const uint32_t* a, const uint32_t* b){
    asm volatile("mma.sync.aligned.m16n8k16.row.col.f32.bf16.bf16.f32 "
        "{%0,%1,%2,%3}, {%4,%5,%6,%7}, {%8,%9}, {%0,%1,%2,%3};"
        : "+f"(c[0]), "+f"(c[1]), "+f"(c[2]), "+f"(c[3])
        : "r"(a[0]), "r"(a[1]), "r"(a[2]), "r"(a[3]), "r"(b[0]), "r"(b[1]));
}
__device__ __forceinline__ void cp16(uint32_t dst, const void* src){
    asm volatile("cp.async.cg.shared.global [%0], [%1], 16;" :: "r"(dst), "l"(src));
}
#define CP_COMMIT() asm volatile("cp.async.commit_group;" ::: "memory")
#define CP_WAIT0()  asm volatile("cp.async.wait_group 0;" ::: "memory")

// ============================ scratch (device globals) ============================
__device__ float g_x  [N_BT*N_D];
__device__ float g_h  [N_BT*N_D];
__device__ float g_qkv[N_BT*N_QKV];
__device__ float g_att[N_BT*N_D];
__device__ float g_ff [N_BT*N_DF];

// transposed + split weights: [N, K] row-major bf16 (hi, lo)
__device__ __nv_bfloat16 g_wqkv_h[N_L*N_QKV*N_D], g_wqkv_l[N_L*N_QKV*N_D];
__device__ __nv_bfloat16 g_wo_h  [N_L*N_D*N_D],   g_wo_l  [N_L*N_D*N_D];
__device__ __nv_bfloat16 g_w1_h  [N_L*N_DF*N_D],  g_w1_l  [N_L*N_DF*N_D];
__device__ __nv_bfloat16 g_w2_h  [N_L*N_D*N_DF],  g_w2_l  [N_L*N_D*N_DF];
__device__ __nv_bfloat16 g_hd_h  [(size_t)N_V*N_D], g_hd_l [(size_t)N_V*N_D];

// ============================ weight convert (transpose + bf16 split) ============================
// src W [K, N] f32  ->  out [N, K] bf16 hi/lo
__global__ __launch_bounds__(256) void convw_kernel(const float* __restrict__ W,
                                                    __nv_bfloat16* __restrict__ oh,
                                                    __nv_bfloat16* __restrict__ ol,
                                                    int K, int N){
    __shared__ float t[32][33];
    const int n0 = blockIdx.x*32, k0 = blockIdx.y*32;
    const int tx = threadIdx.x & 31, ty = threadIdx.x >> 5;
    #pragma unroll
    for(int r = ty; r < 32; r += 8)
        t[r][tx] = W[(size_t)(k0+r)*N + n0 + tx];
    __syncthreads();
    #pragma unroll
    for(int r = ty; r < 32; r += 8){
        float v = t[tx][r];                       // = W[k0+tx][n0+r]
        __nv_bfloat16 hh = __float2bfloat16(v);
        float rem = v - __bfloat162float(hh);
        size_t o = (size_t)(n0+r)*K + k0 + tx;
        oh[o] = hh;
        ol[o] = __float2bfloat16(rem);
    }
}

// ============================ embedding ============================
__global__ __launch_bounds__(256) void embed_kernel(const int* __restrict__ idx,
                                                    const float* __restrict__ tok,
                                                    const float* __restrict__ pos){
    int bt = blockIdx.x;
    int t  = bt & (N_T-1);
    int token = idx[bt];
    const float* tp = tok + (size_t)token*N_D;
    const float* pp = pos + (size_t)t*N_D;
    float* xp = g_x + (size_t)bt*N_D;
    for(int d = threadIdx.x; d < N_D; d += 256)
        xp[d] = tp[d] + pp[d];
}

// ============================ layernorm ============================
__global__ __launch_bounds__(256) void ln_kernel(const float* __restrict__ in,
                                                 float* __restrict__ out,
                                                 const float* __restrict__ gam,
                                                 const float* __restrict__ bet){
    int row = blockIdx.x;
    int tid = threadIdx.x;
    const float* xr = in + (size_t)row*N_D;
    float v0 = xr[tid], v1 = xr[tid+256], v2 = xr[tid+512];
    __shared__ float red[8];
    float s = v0+v1+v2;
    #pragma unroll
    for(int o=16;o>0;o>>=1) s += __shfl_xor_sync(0xffffffffu, s, o);
    if((tid&31)==0) red[tid>>5] = s;
    __syncthreads();
    float tot = 0.f;
    #pragma unroll
    for(int w=0;w<8;w++) tot += red[w];
    float mu = tot * (1.f/N_D);
    float d0=v0-mu, d1=v1-mu, d2=v2-mu;
    float s2 = d0*d0 + d1*d1 + d2*d2;
    #pragma unroll
    for(int o=16;o>0;o>>=1) s2 += __shfl_xor_sync(0xffffffffu, s2, o);
    __syncthreads();
    if((tid&31)==0) red[tid>>5] = s2;
    __syncthreads();
    float tot2 = 0.f;
    #pragma unroll
    for(int w=0;w<8;w++) tot2 += red[w];
    float rstd = rsqrtf(tot2*(1.f/N_D) + 1e-5f);
    float* orow = out + (size_t)row*N_D;
    orow[tid]     = d0*rstd*gam[tid]     + bet[tid];
    orow[tid+256] = d1*rstd*gam[tid+256] + bet[tid+256];
    orow[tid+512] = d2*rstd*gam[tid+512] + bet[tid+512];
}

// ============================ mma.sync split-bf16 GEMM ============================
// C[M,N] = A[M,K] @ W[K,N]; W provided as Bh/Bl [N,K] bf16 (hi/lo split).
// CTA tile 128x128x32, 8 warps of 64x32, double-buffered cp.async.
// D = Ah*Bh + Ah*Bl + Al*Bh  (fp32 accumulate) -> ~2^-20 relative error.
// EPI: 0 none, 1 +bias, 2 +bias+residual, 3 +bias then exact GELU.
#define BM 128
#define BN 128
#define BK 32
#define SA 40                      // smem stride in halfs (32 + 8 pad)
#define TILE_BYTES (BM*SA*2)       // 10240 B per split tile
#define OFF_AH 0
#define OFF_AL (1*TILE_BYTES)
#define OFF_BH (2*TILE_BYTES)
#define OFF_BL (3*TILE_BYTES)
#define STAGE_BYTES (4*TILE_BYTES) // 40960
#define GEMM_SMEM (2*STAGE_BYTES)  // 81920

template<int EPI>
__global__ void __launch_bounds__(256) gemm_mma(
        const float* __restrict__ A,
        const __nv_bfloat16* __restrict__ Bh,
        const __nv_bfloat16* __restrict__ Bl,
        const float* __restrict__ bias, const float* __restrict__ res,
        float* __restrict__ C, int M, int N, int K){
    extern __shared__ char sm[];
    const uint32_t sb = smem_u32(sm);
    const int tid = threadIdx.x, wid = tid>>5, lane = tid&31;
    const int mBase = blockIdx.x*BM, nBase = blockIdx.y*BN;
    const int wm = (wid>>2)*64, wn = (wid&3)*32;

    const float* Ap = A + (size_t)mBase*K;
    const __nv_bfloat16* Bhp = Bh + (size_t)nBase*K;
    const __nv_bfloat16* Blp = Bl + (size_t)nBase*K;
    const int nk = K / BK;

    float c[4][4][4];
    #pragma unroll
    for(int mt=0;mt<4;mt++)
        #pragma unroll
        for(int nt=0;nt<4;nt++)
            #pragma unroll
            for(int r=0;r<4;r++) c[mt][nt][r] = 0.f;

    // per-thread tile indices
    const int ar0 = tid >> 3, ac = (tid & 7) * 4;          // A: 4 float4, rows ar0 + i*32
    const int br0 = tid >> 2, bs = (tid & 3) * 8;          // B: 2 x16B per split, rows br0 + i*64

    float4 areg[4];
    auto loadA = [&](int k0){
        #pragma unroll
        for(int i=0;i<4;i++)
            areg[i] = *(const float4*)(Ap + (size_t)(ar0 + i*32)*K + k0 + ac);
    };
    auto storeA = [&](int s){
        uint32_t base = sb + s*STAGE_BYTES;
        #pragma unroll
        for(int i=0;i<4;i++){
            float4 f = areg[i];
            __nv_bfloat16 h0=__float2bfloat16(f.x), h1=__float2bfloat16(f.y),
                          h2=__float2bfloat16(f.z), h3=__float2bfloat16(f.w);
            ushort4 hh; hh.x=__bfloat16_as_ushort(h0); hh.y=__bfloat16_as_ushort(h1);
                        hh.z=__bfloat16_as_ushort(h2); hh.w=__bfloat16_as_ushort(h3);
            ushort4 ll;
            ll.x=__bfloat16_as_ushort(__float2bfloat16(f.x-__bfloat162float(h0)));
            ll.y=__bfloat16_as_ushort(__float2bfloat16(f.y-__bfloat162float(h1)));
            ll.z=__bfloat16_as_ushort(__float2bfloat16(f.z-__bfloat162float(h2)));
            ll.w=__bfloat16_as_ushort(__float2bfloat16(f.w-__bfloat162float(h3)));
            uint32_t off = ((ar0 + i*32)*SA + ac)*2;
            *(ushort4*)(sm + s*STAGE_BYTES + OFF_AH + off) = hh;
            *(ushort4*)(sm + s*STAGE_BYTES + OFF_AL + off) = ll;
        }
        (void)base;
    };
    auto prefetchB = [&](int k0, int s){
        uint32_t base = sb + s*STAGE_BYTES;
        #pragma unroll
        for(int i=0;i<2;i++){
            int row = br0 + i*64;
            uint32_t off = (row*SA + bs)*2;
            cp16(base + OFF_BH + off, Bhp + (size_t)row*K + k0 + bs);
            cp16(base + OFF_BL + off, Blp + (size_t)row*K + k0 + bs);
        }
    };

    auto compute = [&](uint32_t stg){
        #pragma unroll
        for(int ks=0;ks<2;ks++){
            uint32_t ah[4][4], al[4][4], bh[4][2], bl[4][2];
            const uint32_t a_lo = (uint32_t)(((lane&15)*SA + ks*16 + (lane>>4)*8)*2);
            #pragma unroll
            for(int mt=0;mt<4;mt++){
                uint32_t a = stg + (uint32_t)(((wm + mt*16)*SA)*2) + a_lo;
                ldsm_x4(ah[mt], a + OFF_AH);
                ldsm_x4(al[mt], a + OFF_AL);
            }
            const uint32_t b_lo = (uint32_t)(((lane&7)*SA + ks*16 + ((lane>>3)&1)*8)*2);
            #pragma unroll
            for(int nt=0;nt<4;nt++){
                uint32_t b = stg + (uint32_t)(((wn + nt*8)*SA)*2) + b_lo;
                ldsm_x2(bh[nt], b + OFF_BH);
                ldsm_x2(bl[nt], b + OFF_BL);
            }
            #pragma unroll
            for(int mt=0;mt<4;mt++)
                #pragma unroll
                for(int nt=0;nt<4;nt++){
                    mma_bf16(c[mt][nt], ah[mt], bh[nt]);
                    mma_bf16(c[mt][nt], ah[mt], bl[nt]);
                    mma_bf16(c[mt][nt], al[mt], bh[nt]);
                }
        }
    };

    // prologue: fill stage 0
    prefetchB(0, 0); CP_COMMIT();
    loadA(0);
    storeA(0);
    CP_WAIT0();
    __syncthreads();

    for(int i=0;i<nk;i++){
        const int s = i & 1;
        if(i+1 < nk){
            prefetchB((i+1)*BK, s^1); CP_COMMIT();
            loadA((i+1)*BK);
        }
        compute(sb + s*STAGE_BYTES);
        if(i+1 < nk){
            storeA(s^1);
            CP_WAIT0();
            __syncthreads();
        }
    }

    // ---- epilogue ----
    const int g = lane>>2, t2 = (lane&3)*2;
    #pragma unroll
    for(int mt=0;mt<4;mt++){
        const int row0 = mBase + wm + mt*16 + g;
        #pragma unroll
        for(int nt=0;nt<4;nt++){
            const int col = nBase + wn + nt*8 + t2;
            float v[4] = { c[mt][nt][0], c[mt][nt][1], c[mt][nt][2], c[mt][nt][3] };
            if(EPI != 0){
                float2 b2 = *(const float2*)(bias + col);
                v[0]+=b2.x; v[1]+=b2.y; v[2]+=b2.x; v[3]+=b2.y;
            }
            if(EPI == 2){
                float2 r0 = *(const float2*)(res + (size_t)row0*N + col);
                float2 r1 = *(const float2*)(res + (size_t)(row0+8)*N + col);
                v[0]+=r0.x; v[1]+=r0.y; v[2]+=r1.x; v[3]+=r1.y;
            }
            if(EPI == 3){
                #pragma unroll
                for(int r=0;r<4;r++) v[r] = 0.5f*v[r]*(1.f + erff(v[r]*0.70710678118654752f));
            }
            *(float2*)(C + (size_t)row0*N + col)     = make_float2(v[0], v[1]);
            *(float2*)(C + (size_t)(row0+8)*N + col) = make_float2(v[2], v[3]);
        }
    }
}

// ============================ fused causal flash attention (fp32 SIMT) ============================
// QKV packed [B*T, 2304]: Q at col h*64, K at 768+h*64, V at 1536+h*64.
#define APAD 65
#define ATT_SMEM (3*64*APAD*4)
#define QKV_S N_QKV

__global__ __launch_bounds__(256) void attn_kernel(const float* __restrict__ QKV,
                                                   float* __restrict__ O){
    extern __shared__ float smf[];
    float* Qs  = smf;
    float* KVs = smf + 64*APAD;
    float* Ps  = smf + 2*64*APAD;
    const int qtile = blockIdx.x;
    const int bh = blockIdx.y;
    const int b = bh / N_H, h = bh % N_H;
    const int tid = threadIdx.x;
    const int tr = tid >> 4, tc = tid & 15;
    const float* Qb = QKV + (size_t)b*N_T*QKV_S + h*64;
    const float* Kb = Qb + N_D;
    const float* Vb = Qb + 2*N_D;

    for(int v4 = tid; v4 < 1024; v4 += 256){
        int r = v4 >> 4, c = (v4 & 15) << 2;
        float4 f = *(const float4*)(Qb + (size_t)(qtile*64 + r)*QKV_S + c);
        float* d = Qs + r*APAD + c;
        d[0]=f.x; d[1]=f.y; d[2]=f.z; d[3]=f.w;
    }

    float m_[4], l_[4], acc[4][4];
    #pragma unroll
    for(int i=0;i<4;i++){
        m_[i] = -1e30f; l_[i] = 0.f;
        #pragma unroll
        for(int j=0;j<4;j++) acc[i][j] = 0.f;
    }

    for(int kt = 0; kt <= qtile; kt++){
        for(int v4 = tid; v4 < 1024; v4 += 256){
            int r = v4 >> 4, c = (v4 & 15) << 2;
            float4 f = *(const float4*)(Kb + (size_t)(kt*64 + r)*QKV_S + c);
            float* d = KVs + r*APAD + c;
            d[0]=f.x; d[1]=f.y; d[2]=f.z; d[3]=f.w;
        }
        __syncthreads();

        float s[4][4];
        #pragma unroll
        for(int i=0;i<4;i++)
            #pragma unroll
            for(int j=0;j<4;j++) s[i][j] = 0.f;
        #pragma unroll 8
        for(int kk=0;kk<64;kk++){
            float qa[4], ka[4];
            #pragma unroll
            for(int i=0;i<4;i++) qa[i] = Qs[(tr*4+i)*APAD + kk];
            #pragma unroll
            for(int j=0;j<4;j++) ka[j] = KVs[(tc*4+j)*APAD + kk];
            #pragma unroll
            for(int i=0;i<4;i++)
                #pragma unroll
                for(int j=0;j<4;j++) s[i][j] += qa[i]*ka[j];
        }
        const float scl = 0.125f;
        if(kt == qtile){
            #pragma unroll
            for(int i=0;i<4;i++)
                #pragma unroll
                for(int j=0;j<4;j++)
                    s[i][j] = (tc*4+j <= tr*4+i) ? s[i][j]*scl : -1e30f;
        } else {
            #pragma unroll
            for(int i=0;i<4;i++)
                #pragma unroll
                for(int j=0;j<4;j++) s[i][j] *= scl;
        }

        #pragma unroll
        for(int i=0;i<4;i++){
            float rm = fmaxf(fmaxf(s[i][0],s[i][1]), fmaxf(s[i][2],s[i][3]));
            #pragma unroll
            for(int o=8;o>0;o>>=1) rm = fmaxf(rm, __shfl_xor_sync(0xffffffffu, rm, o));
            float mn = fmaxf(m_[i], rm);
            float corr = expf(m_[i] - mn);
            m_[i] = mn;
            float rs = 0.f;
            #pragma unroll
            for(int j=0;j<4;j++){ float p = expf(s[i][j] - mn); s[i][j] = p; rs += p; }
            #pragma unroll
            for(int o=8;o>0;o>>=1) rs += __shfl_xor_sync(0xffffffffu, rs, o);
            l_[i] = l_[i]*corr + rs;
            #pragma unroll
            for(int j=0;j<4;j++){ acc[i][j] *= corr; Ps[(tr*4+i)*APAD + tc*4+j] = s[i][j]; }
        }
        __syncthreads();

        for(int v4 = tid; v4 < 1024; v4 += 256){
            int r = v4 >> 4, c = (v4 & 15) << 2;
            float4 f = *(const float4*)(Vb + (size_t)(kt*64 + r)*QKV_S + c);
            float* d = KVs + r*APAD + c;
            d[0]=f.x; d[1]=f.y; d[2]=f.z; d[3]=f.w;
        }
        __syncthreads();

        #pragma unroll 8
        for(int kk=0;kk<64;kk++){
            float pa[4], va[4];
            #pragma unroll
            for(int i=0;i<4;i++) pa[i] = Ps[(tr*4+i)*APAD + kk];
            #pragma unroll
            for(int j=0;j<4;j++) va[j] = KVs[kk*APAD + tc*4 + j];
            #pragma unroll
            for(int i=0;i<4;i++)
                #pragma unroll
                for(int j=0;j<4;j++) acc[i][j] += pa[i]*va[j];
        }
        __syncthreads();
    }

    float* Ob = O + (size_t)b*N_T*N_D + h*64;
    #pragma unroll
    for(int i=0;i<4;i++){
        float inv = 1.f / l_[i];
        int r = qtile*64 + tr*4 + i;
        *(float4*)(Ob + (size_t)r*N_D + tc*4) =
            make_float4(acc[i][0]*inv, acc[i][1]*inv, acc[i][2]*inv, acc[i][3]*inv);
    }
}

// ============================ host orchestration ============================
extern "C" void kernel_launch(void* const* d_in, const int* in_sizes, int n_in,
                              void* d_out, int out_size){
    const int*   idx   = (const int*)  d_in[0];
    const float* tok   = (const float*)d_in[1];
    const float* pos   = (const float*)d_in[2];
    const float* Wq    = (const float*)d_in[3];
    const float* Wk    = (const float*)d_in[4];
    const float* Wv    = (const float*)d_in[5];
    const float* Wo    = (const float*)d_in[6];
    const float* bo    = (const float*)d_in[7];
    const float* W1    = (const float*)d_in[8];
    const float* b1    = (const float*)d_in[9];
    const float* W2    = (const float*)d_in[10];
    const float* b2    = (const float*)d_in[11];
    const float* ln1g  = (const float*)d_in[12];
    const float* ln1b  = (const float*)d_in[13];
    const float* ln2g  = (const float*)d_in[14];
    const float* ln2b  = (const float*)d_in[15];
    const float* lnfg  = (const float*)d_in[16];
    const float* lnfb  = (const float*)d_in[17];
    const float* headW = (const float*)d_in[18];
    const float* headb = (const float*)d_in[19];
    float* out = (float*)d_out;

    float *x,*h,*qkv,*att,*ff;
    cudaGetSymbolAddress((void**)&x,   g_x);
    cudaGetSymbolAddress((void**)&h,   g_h);
    cudaGetSymbolAddress((void**)&qkv, g_qkv);
    cudaGetSymbolAddress((void**)&att, g_att);
    cudaGetSymbolAddress((void**)&ff,  g_ff);
    __nv_bfloat16 *wqkvh,*wqkvl,*woh,*wol,*w1h,*w1l,*w2h,*w2l,*hdh,*hdl;
    cudaGetSymbolAddress((void**)&wqkvh, g_wqkv_h);
    cudaGetSymbolAddress((void**)&wqkvl, g_wqkv_l);
    cudaGetSymbolAddress((void**)&woh,   g_wo_h);
    cudaGetSymbolAddress((void**)&wol,   g_wo_l);
    cudaGetSymbolAddress((void**)&w1h,   g_w1_h);
    cudaGetSymbolAddress((void**)&w1l,   g_w1_l);
    cudaGetSymbolAddress((void**)&w2h,   g_w2_h);
    cudaGetSymbolAddress((void**)&w2l,   g_w2_l);
    cudaGetSymbolAddress((void**)&hdh,   g_hd_h);
    cudaGetSymbolAddress((void**)&hdl,   g_hd_l);

    cudaFuncSetAttribute(attn_kernel, cudaFuncAttributeMaxDynamicSharedMemorySize, ATT_SMEM);
    cudaFuncSetAttribute(gemm_mma<0>, cudaFuncAttributeMaxDynamicSharedMemorySize, GEMM_SMEM);
    cudaFuncSetAttribute(gemm_mma<1>, cudaFuncAttributeMaxDynamicSharedMemorySize, GEMM_SMEM);
    cudaFuncSetAttribute(gemm_mma<2>, cudaFuncAttributeMaxDynamicSharedMemorySize, GEMM_SMEM);
    cudaFuncSetAttribute(gemm_mma<3>, cudaFuncAttributeMaxDynamicSharedMemorySize, GEMM_SMEM);

    // ---- weight conversion: transpose to [N,K] + bf16 hi/lo split ----
    const dim3 gDD(N_D/32,  N_D/32);
    const dim3 gDF1(N_DF/32, N_D/32);  // W1: N=3072, K=768
    const dim3 gDF2(N_D/32,  N_DF/32); // W2: N=768, K=3072
    for(int l=0;l<N_L;l++){
        size_t qkvOff = (size_t)l*N_QKV*N_D;
        convw_kernel<<<gDD,256>>>(Wq + (size_t)l*N_D*N_D, wqkvh + qkvOff,                     wqkvl + qkvOff,                     N_D, N_D);
        convw_kernel<<<gDD,256>>>(Wk + (size_t)l*N_D*N_D, wqkvh + qkvOff + (size_t)N_D*N_D,   wqkvl + qkvOff + (size_t)N_D*N_D,   N_D, N_D);
        convw_kernel<<<gDD,256>>>(Wv + (size_t)l*N_D*N_D, wqkvh + qkvOff + (size_t)2*N_D*N_D, wqkvl + qkvOff + (size_t)2*N_D*N_D, N_D, N_D);
        convw_kernel<<<gDD,256>>>(Wo + (size_t)l*N_D*N_D, woh + (size_t)l*N_D*N_D, wol + (size_t)l*N_D*N_D, N_D, N_D);
        convw_kernel<<<gDF1,256>>>(W1 + (size_t)l*N_D*N_DF, w1h + (size_t)l*N_DF*N_D, w1l + (size_t)l*N_DF*N_D, N_D, N_DF);
        convw_kernel<<<gDF2,256>>>(W2 + (size_t)l*N_DF*N_D, w2h + (size_t)l*N_D*N_DF, w2l + (size_t)l*N_D*N_DF, N_DF, N_D);
    }
    convw_kernel<<<dim3(N_V/32, N_D/32),256>>>(headW, hdh, hdl, N_D, N_V);

    embed_kernel<<<N_BT, 256>>>(idx, tok, pos);

    const dim3 gQKV(N_BT/BM, N_QKV/BN);  // 32 x 18
    const dim3 gOUT(N_BT/BM, N_D/BN);    // 32 x 6
    const dim3 gFF1(N_BT/BM, N_DF/BN);   // 32 x 24
    const dim3 gHead(N_BT/BM, N_V/BN);   // 32 x 250
    const dim3 gAtt(N_T/64, N_Bc*N_H);   // 16 x 48

    for(int l=0;l<N_L;l++){
        ln_kernel<<<N_BT,256>>>(x, h, ln1g + l*N_D, ln1b + l*N_D);
        gemm_mma<0><<<gQKV,256,GEMM_SMEM>>>(h, wqkvh + (size_t)l*N_QKV*N_D, wqkvl + (size_t)l*N_QKV*N_D,
                                            nullptr, nullptr, qkv, N_BT, N_QKV, N_D);
        attn_kernel<<<gAtt,256,ATT_SMEM>>>(qkv, att);
        gemm_mma<2><<<gOUT,256,GEMM_SMEM>>>(att, woh + (size_t)l*N_D*N_D, wol + (size_t)l*N_D*N_D,
                                            bo + l*N_D, x, x, N_BT, N_D, N_D);
        ln_kernel<<<N_BT,256>>>(x, h, ln2g + l*N_D, ln2b + l*N_D);
        gemm_mma<3><<<gFF1,256,GEMM_SMEM>>>(h, w1h + (size_t)l*N_DF*N_D, w1l + (size_t)l*N_DF*N_D,
                                            b1 + l*N_DF, nullptr, ff, N_BT, N_DF, N_D);
        gemm_mma<2><<<gOUT,256,GEMM_SMEM>>>(ff, w2h + (size_t)l*N_D*N_DF, w2l + (size_t)l*N_D*N_DF,
                                            b2 + l*N_D, x, x, N_BT, N_D, N_DF);
    }
    ln_kernel<<<N_BT,256>>>(x, h, lnfg, lnfb);
    gemm_mma<1><<<gHead,256,GEMM_SMEM>>>(h, hdh, hdl, headb, nullptr, out, N_BT, N_V, N_D);
}